// round 15
// baseline (speedup 1.0000x reference)
#include <cuda_runtime.h>
#include <cuda_bf16.h>

typedef unsigned int u32;
typedef unsigned long long u64;

// Problem constants
#define BB 4
#define CC 64
#define HH 192
#define WW 192
#define CS (HH*WW)            // channel stride = 36864
#define NT (BB*CC*HH*WW)      // elems per [B,C,H,W] fp32 tensor
#define NPIX (BB*HH*WW)       // pixels per tensor = 147456
#define VPLANE 4718592        // u32 per v-pair plane: 4*64*192*96

// ---------------- static scratch (no runtime allocation allowed) ----------------
__device__ uint4 g_low1p[NPIX * 16];
__device__ uint4 g_low2p[NPIX * 16];
__device__ uint4 g_tp[4 * NPIX * 16];   // packed conv1 outputs, per combo
__device__ uint4 g_ap[4 * NPIX * 16];   // packed conv2 outputs, per combo
__device__ uint4 g_qkp[4 * NPIX * 16];  // packed conv3 outputs: Q1,K1,Q2,K2
__device__ uint4 g_wp[5][9216];         // prepacked weights
__device__ u32   g_lv[2][2][VPLANE];    // v-pair packed low1/low2: [tensor][hi/lo]
__device__ float g_r2l1[NT];
__device__ float g_l2r1[NT];

// ---------------- helpers ----------------
__device__ __forceinline__ void split_pack(float ev, float ov, u32 &hi, u32 &lo)
{
    __nv_bfloat16 eh = __float2bfloat16(ev);
    __nv_bfloat16 oh = __float2bfloat16(ov);
    __nv_bfloat16 el = __float2bfloat16(ev - __bfloat162float(eh));
    __nv_bfloat16 ol = __float2bfloat16(ov - __bfloat162float(oh));
    hi = (u32)__bfloat16_as_ushort(eh) | ((u32)__bfloat16_as_ushort(oh) << 16);
    lo = (u32)__bfloat16_as_ushort(el) | ((u32)__bfloat16_as_ushort(ol) << 16);
}

__device__ __forceinline__ void mma16816(float c[4],
                                         u32 a0, u32 a1, u32 a2, u32 a3,
                                         u32 b0, u32 b1)
{
    asm volatile(
        "mma.sync.aligned.m16n8k16.row.col.f32.bf16.bf16.f32 "
        "{%0,%1,%2,%3}, {%4,%5,%6,%7}, {%8,%9}, {%0,%1,%2,%3};"
        : "+f"(c[0]), "+f"(c[1]), "+f"(c[2]), "+f"(c[3])
        : "r"(a0), "r"(a1), "r"(a2), "r"(a3), "r"(b0), "r"(b1));
}

__device__ __forceinline__ void ldsm4(u32 f[4], u32 addr)
{
    asm volatile(
        "ldmatrix.sync.aligned.m8n8.x4.shared.b16 {%0,%1,%2,%3}, [%4];"
        : "=r"(f[0]), "=r"(f[1]), "=r"(f[2]), "=r"(f[3]) : "r"(addr));
}

__device__ __forceinline__ void ldsm4t(u32 f[4], u32 addr)
{
    asm volatile(
        "ldmatrix.sync.aligned.m8n8.x4.trans.shared.b16 {%0,%1,%2,%3}, [%4];"
        : "=r"(f[0]), "=r"(f[1]), "=r"(f[2]), "=r"(f[3]) : "r"(addr));
}

// =================================================================================
// Single merged prep kernel: weights + NHWC features + v-pair features
// =================================================================================
#define NH_ITEMS (2 * 16 * NPIX)            // uint4 items, NHWC part
#define VP_ITEMS (2 * (VPLANE / 4))         // uint4 items, v-pair part
#define WT_ITEMS (5 * 9216)                 // uint4 items, weights part
#define PREP_TOTAL (NH_ITEMS + VP_ITEMS + WT_ITEMS)

__global__ void prep_all(const float* __restrict__ x1,
                         const float* __restrict__ x2,
                         const float* __restrict__ w0, const float* __restrict__ w1,
                         const float* __restrict__ w2, const float* __restrict__ w3,
                         const float* __restrict__ w4,
                         uint4* __restrict__ xp1, uint4* __restrict__ xp2,
                         u32* __restrict__ lv, uint4* __restrict__ wp)
{
    int gi = blockIdx.x * 256 + threadIdx.x;
    if (gi < NH_ITEMS) {
        int tsel = gi / (16 * NPIX);
        int r = gi - tsel * 16 * NPIX;
        int j = r / NPIX;
        int p = r - j * NPIX;
        const float* x = tsel ? x2 : x1;
        uint4* xp = tsel ? xp2 : xp1;
        int b = p / (HH * WW);
        int pos = p - b * HH * WW;
        const float* src = x + (size_t)(b * 64 + 4 * j) * CS + pos;
        u32 h0, l0, h1, l1;
        split_pack(src[0], src[CS], h0, l0);
        split_pack(src[2 * CS], src[3 * CS], h1, l1);
        xp[(size_t)p * 16 + j] = make_uint4(h0, l0, h1, l1);
        return;
    }
    int vi = gi - NH_ITEMS;
    if (vi < VP_ITEMS) {
        const int PER = VPLANE / 4;
        int tsel = vi / PER;
        int r = vi - tsel * PER;             // (bch)*24 + q4
        int q4 = r % 24;
        int bch = r / 24;
        const float* x = tsel ? x2 : x1;
        const float* src = x + (size_t)bch * WW + q4 * 8;
        float4 f0 = *(const float4*)src;
        float4 f1 = *(const float4*)(src + 4);
        u32 h0, l0, h1, l1, h2, l2, h3, l3;
        split_pack(f0.x, f0.y, h0, l0);
        split_pack(f0.z, f0.w, h1, l1);
        split_pack(f1.x, f1.y, h2, l2);
        split_pack(f1.z, f1.w, h3, l3);
        uint4* hi = (uint4*)(lv + ((size_t)tsel * 2 + 0) * VPLANE);
        uint4* lo = (uint4*)(lv + ((size_t)tsel * 2 + 1) * VPLANE);
        hi[r] = make_uint4(h0, h1, h2, h3);
        lo[r] = make_uint4(l0, l1, l2, l3);
        return;
    }
    int wi = vi - VP_ITEMS;
    if (wi >= WT_ITEMS) return;
    int which = wi / 9216, r = wi % 9216;
    const float* w = (which == 0) ? w0 : (which == 1) ? w1 :
                     (which == 2) ? w2 : (which == 3) ? w3 : w4;
    int tap = r >> 10, rem = r & 1023;
    int chunk = rem >> 8, rem2 = rem & 255;
    int o = rem2 >> 2, t = rem2 & 3;
    int c2a = chunk * 8 + t, c2b = c2a + 4;
    u32 h0, l0, h1, l1;
    split_pack(__ldg(&w[o * 576 + (2 * c2a) * 9 + tap]),
               __ldg(&w[o * 576 + (2 * c2a + 1) * 9 + tap]), h0, l0);
    split_pack(__ldg(&w[o * 576 + (2 * c2b) * 9 + tap]),
               __ldg(&w[o * 576 + (2 * c2b + 1) * 9 + tap]), h1, l1);
    wp[wi] = make_uint4(h0, h1, l0, l1);
}

// =================================================================================
// Tensor-core conv 3x3 (best config; bias pre-loaded into accumulators).
// =================================================================================
#define CONV_SMEM_BYTES (23040*4)

__global__ void __launch_bounds__(256, 2) conv3x3_tc(
    const uint4* __restrict__ xpA, const uint4* __restrict__ xpB, int xstride_u4,
    const uint4* __restrict__ wpA, const uint4* __restrict__ wpB,
    const float* __restrict__ bsA, const float* __restrict__ bsB,
    const float* __restrict__ skA, const float* __restrict__ skB,
    uint4* __restrict__ yp, int mode)
{
    extern __shared__ u32 smc[];
    u32* Hhi = smc;
    u32* Hlo = smc + 11520;

    const int bz = blockIdx.z;
    const int combo = bz >> 2, b = bz & 3;
    const uint4* xp = ((combo & 1) ? xpB : xpA) + (size_t)combo * xstride_u4;
    const uint4* wp = (combo >> 1) ? wpB : wpA;
    const float* bias = (combo >> 1) ? bsB : bsA;
    const float* skip = (combo & 1) ? skB : skA;

    const int ty = blockIdx.y, tx = blockIdx.x;
    const int tid = threadIdx.x, wid = tid >> 5, lane = tid & 31;
    const int g = lane >> 2, t = lane & 3;
    const int wr = wid & 3, wh = wid >> 2;

    // bias preload (latency hidden behind halo staging)
    float bv[4][2];
#pragma unroll
    for (int n8l = 0; n8l < 4; n8l++) {
        const int och0 = (wh * 4 + n8l) * 8 + 2 * t;
        bv[n8l][0] = __ldg(&bias[och0]);
        bv[n8l][1] = __ldg(&bias[och0 + 1]);
    }

    const int y0 = ty * 16 - 1, x0 = tx * 16 - 1;
    for (int i = tid; i < 324 * 16; i += 256) {
        int pix = i >> 4, j = i & 15;
        int yy = pix / 18, xx = pix - yy * 18;
        int gy = y0 + yy, gx = x0 + xx;
        uint4 v = make_uint4(0u, 0u, 0u, 0u);
        if (gy >= 0 && gy < HH && gx >= 0 && gx < WW)
            v = __ldg(&xp[(size_t)((b * HH + gy) * WW + gx) * 16 + j]);
        int unitoff = (yy * 20 + xx) * 32 + (((j >> 1) ^ (xx & 7)) << 2) + ((j & 1) << 1);
        *(uint2*)&Hhi[unitoff] = make_uint2(v.x, v.z);
        *(uint2*)&Hlo[unitoff] = make_uint2(v.y, v.w);
    }
    __syncthreads();

    float acc[4][4][4];
#pragma unroll
    for (int mi = 0; mi < 4; mi++)
#pragma unroll
        for (int n8 = 0; n8 < 4; n8++)
#pragma unroll
            for (int q = 0; q < 4; q++) acc[mi][n8][q] = bv[n8][q & 1];

    const int row0 = 4 * wr;
    const u32 hbase = (u32)__cvta_generic_to_shared(Hhi);
    const u32 lbase = (u32)__cvta_generic_to_shared(Hlo);
    const int m = lane & 15, half = lane >> 4;

    for (int ch = 0; ch < 4; ch++) {
#pragma unroll
        for (int dx = 0; dx < 3; dx++) {
            const int xm = dx + m;
            const int coff = (((ch * 2 + half) ^ (xm & 7)) << 4);
            const u32 a0 = (u32)((row0 * 20 + xm) * 128 + coff);
            u32 fh[6][4], fl[6][4];
#pragma unroll
            for (int ri = 0; ri < 6; ri++) {
                ldsm4(fh[ri], hbase + a0 + ri * 2560);
                ldsm4(fl[ri], lbase + a0 + ri * 2560);
            }
#pragma unroll
            for (int dy = 0; dy < 3; dy++) {
                const uint4* wrow = wp + (((dy * 3 + dx) * 4 + ch) * 64) * 4 + t;
                uint4 Bnext = __ldg(&wrow[((wh * 4) * 8 + g) * 4]);
#pragma unroll
                for (int n8l = 0; n8l < 4; n8l++) {
                    const uint4 Bc = Bnext;
                    if (n8l < 3)
                        Bnext = __ldg(&wrow[(((wh * 4 + n8l + 1)) * 8 + g) * 4]);
#pragma unroll
                    for (int mi = 0; mi < 4; mi++) {
                        const int ri = mi + dy;
                        mma16816(acc[mi][n8l], fh[ri][0], fh[ri][1], fh[ri][2], fh[ri][3], Bc.x, Bc.y);
                    }
#pragma unroll
                    for (int mi = 0; mi < 4; mi++) {
                        const int ri = mi + dy;
                        mma16816(acc[mi][n8l], fh[ri][0], fh[ri][1], fh[ri][2], fh[ri][3], Bc.z, Bc.w);
                    }
#pragma unroll
                    for (int mi = 0; mi < 4; mi++) {
                        const int ri = mi + dy;
                        mma16816(acc[mi][n8l], fl[ri][0], fl[ri][1], fl[ri][2], fl[ri][3], Bc.x, Bc.y);
                    }
                }
            }
        }
    }

    const int gyb = ty * 16 + row0, gxb = tx * 16;
    uint2* ypc = (uint2*)(yp + (size_t)combo * (NPIX * 16));
#pragma unroll
    for (int n8l = 0; n8l < 4; n8l++) {
        const int n8g = wh * 4 + n8l;
        const int och0 = n8g * 8 + 2 * t;
        const int c2o = n8g * 4 + t;
#pragma unroll
        for (int mi = 0; mi < 4; mi++) {
            const int gy = gyb + mi;
#pragma unroll
            for (int hlf = 0; hlf < 2; hlf++) {
                const int px = gxb + g + hlf * 8;
                float v0 = acc[mi][n8l][hlf * 2 + 0];
                float v1 = acc[mi][n8l][hlf * 2 + 1];
                if (mode == 1) {
                    v0 = fmaxf(v0, 0.f);
                    v1 = fmaxf(v1, 0.f);
                } else if (mode == 2) {
                    const int off = ((b * 64 + och0) * HH + gy) * WW + px;
                    v0 += __ldg(&skip[off]);
                    v1 += __ldg(&skip[off + CS]);
                }
                u32 h, l;
                split_pack(v0, v1, h, l);
                ypc[(size_t)((b * HH + gy) * WW + px) * 32 + c2o] = make_uint2(h, l);
            }
        }
    }
}

// =================================================================================
// Tensor-core attention (best-measured config, unchanged from R14).
// =================================================================================
#define SL_B   73728
#define QSH_U  0
#define QSL_U  6144
#define KH_U   12288
#define KL_U   19200
#define FH_U   36864
#define FL_U   43264
#define ATTN_SMEM 198656

__device__ __forceinline__ void qk_ldg(uint4 vq[8], uint4 vk[8],
                                       const uint4* __restrict__ q,
                                       const uint4* __restrict__ k,
                                       int pixbase, int tid)
{
#pragma unroll
    for (int it = 0; it < 8; it++) {
        int i = tid + it * 384;
        int p = i >> 4, j = i & 15;
        vq[it] = __ldg(&q[(size_t)(pixbase + p) * 16 + j]);
        vk[it] = __ldg(&k[(size_t)(pixbase + p) * 16 + j]);
    }
}

__device__ __forceinline__ void qk_sts(u32* sm, const uint4 vq[8],
                                       const uint4 vk[8], int tid)
{
#pragma unroll
    for (int it = 0; it < 8; it++) {
        int i = tid + it * 384;
        int p = i >> 4, j = i & 15;
        int us = (j >> 1) ^ (p & 7);
        int qoff = p * 32 + us * 4 + (j & 1) * 2;
        *(uint2*)(sm + QSH_U + qoff) = make_uint2(vq[it].x, vq[it].z);
        *(uint2*)(sm + QSL_U + qoff) = make_uint2(vq[it].y, vq[it].w);
        int koff = p * 36 + 2 * j;
        *(uint2*)(sm + KH_U + koff) = make_uint2(vk[it].x, vk[it].z);
        *(uint2*)(sm + KL_U + koff) = make_uint2(vk[it].y, vk[it].w);
    }
}

__device__ __forceinline__ void compute_store_S(u32* sm, u32 smem_base,
                                                int wid, int lane)
{
    const int g = lane >> 2, t = lane & 3;
    const int w0 = wid * 16;
    const int tile = lane >> 3, lr = lane & 7;
    const int arow = w0 + lr + ((tile & 1) << 3);

    float acc[24][4];
#pragma unroll
    for (int n8 = 0; n8 < 24; n8++)
#pragma unroll
        for (int q = 0; q < 4; q++) acc[n8][q] = 0.f;

    const u32* kh = sm + KH_U;
    const u32* kl = sm + KL_U;

#pragma unroll
    for (int ch = 0; ch < 4; ch++) {
        const int ut = 2 * ch + (tile >> 1);
        const int us = ut ^ (arow & 7);
        const u32 qaddr = smem_base + (u32)(arow * 128 + us * 16);
        u32 ah[4], al[4];
        ldsm4(ah, qaddr);
        ldsm4(al, qaddr + 24576);
        const int kbase = ch * 8 + t;
#pragma unroll
        for (int n8 = 0; n8 < 24; n8++) {
            const int p36 = (n8 * 8 + g) * 36;
            u32 b0h = kh[p36 + kbase], b1h = kh[p36 + kbase + 4];
            u32 b0l = kl[p36 + kbase], b1l = kl[p36 + kbase + 4];
            mma16816(acc[n8], ah[0], ah[1], ah[2], ah[3], b0h, b1h);
            mma16816(acc[n8], ah[0], ah[1], ah[2], ah[3], b0l, b1l);
            mma16816(acc[n8], al[0], al[1], al[2], al[3], b0h, b1h);
        }
    }

    float m0 = -1e30f, m1 = -1e30f;
#pragma unroll
    for (int n8 = 0; n8 < 24; n8++) {
        m0 = fmaxf(m0, fmaxf(acc[n8][0], acc[n8][1]));
        m1 = fmaxf(m1, fmaxf(acc[n8][2], acc[n8][3]));
    }
    m0 = fmaxf(m0, __shfl_xor_sync(0xffffffffu, m0, 1));
    m0 = fmaxf(m0, __shfl_xor_sync(0xffffffffu, m0, 2));
    m1 = fmaxf(m1, __shfl_xor_sync(0xffffffffu, m1, 1));
    m1 = fmaxf(m1, __shfl_xor_sync(0xffffffffu, m1, 2));
    float s0 = 0.f, s1 = 0.f;
#pragma unroll
    for (int n8 = 0; n8 < 24; n8++) {
        acc[n8][0] = __expf(acc[n8][0] - m0);
        acc[n8][1] = __expf(acc[n8][1] - m0);
        acc[n8][2] = __expf(acc[n8][2] - m1);
        acc[n8][3] = __expf(acc[n8][3] - m1);
        s0 += acc[n8][0] + acc[n8][1];
        s1 += acc[n8][2] + acc[n8][3];
    }
    s0 += __shfl_xor_sync(0xffffffffu, s0, 1);
    s0 += __shfl_xor_sync(0xffffffffu, s0, 2);
    s1 += __shfl_xor_sync(0xffffffffu, s1, 1);
    s1 += __shfl_xor_sync(0xffffffffu, s1, 2);
    const float inv0 = 1.0f / s0, inv1 = 1.0f / s1;

    __syncthreads();   // all warps done reading Qs/Ks before S overwrites them

    u32* shp = sm;
    u32* slp = sm + SL_B / 4;
    const int rg = w0 + g;
#pragma unroll
    for (int n8 = 0; n8 < 24; n8++) {
        const int us = (n8 & 24) | ((n8 & 7) ^ (rg & 7));
        const int off = us * 4 + t;
        u32 h, l;
        split_pack(acc[n8][0] * inv0, acc[n8][1] * inv0, h, l);
        shp[rg * 96 + off] = h;
        slp[rg * 96 + off] = l;
        split_pack(acc[n8][2] * inv1, acc[n8][3] * inv1, h, l);
        shp[(rg + 8) * 96 + off] = h;
        slp[(rg + 8) * 96 + off] = l;
    }
}

// ---- v-pair F loads (prepacked; pure copy) ----
__device__ __forceinline__ void fv_ldg(uint4 fa[4], uint4 fb[4],
                                       const uint4* __restrict__ vh,
                                       const uint4* __restrict__ vl,
                                       int vbase4, int tid)
{
#pragma unroll
    for (int it = 0; it < 4; it++) {
        int i4 = tid + it * 384;
        int c = i4 / 24, q4 = i4 - c * 24;
        fa[it] = __ldg(&vh[vbase4 + c * 4608 + q4]);
        fb[it] = __ldg(&vl[vbase4 + c * 4608 + q4]);
    }
}

__device__ __forceinline__ void fv_sts(u32* sm, const uint4 fa[4],
                                       const uint4 fb[4], int tid)
{
#pragma unroll
    for (int it = 0; it < 4; it++) {
        int i4 = tid + it * 384;
        int c = i4 / 24, q4 = i4 - c * 24;
        *(uint4*)(sm + FH_U + c * 100 + q4 * 4) = fa[it];
        *(uint4*)(sm + FL_U + c * 100 + q4 * 4) = fb[it];
    }
}

// ---- fp32 two-source sum F load (for stage-2 fused applies) ----
__device__ __forceinline__ void f2_ldg(float4 f[8], const float* __restrict__ sA,
                                       const float* __restrict__ sB,
                                       int rb, int tid)
{
#pragma unroll
    for (int it = 0; it < 8; it++) {
        int i = tid + it * 384;
        int c = i / 48, q = i - c * 48;
        float4 fa = *(const float4*)(sA + rb + c * CS + q * 4);
        float4 fb = *(const float4*)(sB + rb + c * CS + q * 4);
        f[it] = make_float4(fa.x + fb.x, fa.y + fb.y, fa.z + fb.z, fa.w + fb.w);
    }
}

__device__ __forceinline__ void f2_sts(u32* sm, const float4 f[8], int tid)
{
#pragma unroll
    for (int it = 0; it < 8; it++) {
        int i = tid + it * 384;
        int c = i / 48, q = i - c * 48;
        u32 h0, l0, h1, l1;
        split_pack(f[it].x, f[it].y, h0, l0);
        split_pack(f[it].z, f[it].w, h1, l1);
        *(uint2*)(sm + FH_U + c * 100 + 2 * q) = make_uint2(h0, h1);
        *(uint2*)(sm + FL_U + c * 100 + 2 * q) = make_uint2(l0, l1);
    }
}

template <bool TR>
__device__ __forceinline__ void apply_tc(u32* sm, u32 smem_base,
                                         int wid, int lane, float acc[8][4])
{
    const int g = lane >> 2, t = lane & 3;
    const int w0 = wid * 16;
    const int tile = lane >> 3, lr = lane & 7;
    const u32* fh = sm + FH_U;
    const u32* fl = sm + FL_U;

#pragma unroll
    for (int n8 = 0; n8 < 8; n8++)
#pragma unroll
        for (int q = 0; q < 4; q++) acc[n8][q] = 0.f;

#pragma unroll
    for (int k = 0; k < 12; k++) {
        u32 ah[4], al[4];
        if (!TR) {
            const int row = w0 + lr + ((tile & 1) << 3);
            const int ut = 2 * k + (tile >> 1);
            const int us = (ut & 24) | ((ut & 7) ^ (row & 7));
            const u32 addr = smem_base + (u32)(row * 384 + us * 16);
            ldsm4(ah, addr);
            ldsm4(al, addr + 73728);
        } else {
            const int srow = k * 16 + lr + ((tile >> 1) << 3);
            const int cu = 2 * wid + (tile & 1);
            const int us = (cu & 24) | ((cu & 7) ^ (srow & 7));
            const u32 addr = smem_base + (u32)(srow * 384 + us * 16);
            ldsm4t(ah, addr);
            ldsm4t(al, addr + 73728);
        }
        const int fb = 8 * k + t;
#pragma unroll
        for (int n8 = 0; n8 < 8; n8++) {
            const int c100 = (n8 * 8 + g) * 100;
            u32 b0h = fh[c100 + fb], b1h = fh[c100 + fb + 4];
            u32 b0l = fl[c100 + fb], b1l = fl[c100 + fb + 4];
            mma16816(acc[n8], ah[0], ah[1], ah[2], ah[3], b0h, b1h);
            mma16816(acc[n8], ah[0], ah[1], ah[2], ah[3], b0l, b1l);
            mma16816(acc[n8], al[0], al[1], al[2], al[3], b0h, b1h);
        }
    }
}

__device__ __forceinline__ void emit_init2(float* dst, float* scratch,
                                           const float* base, const float acc[8][4],
                                           int rb, int wid, int lane)
{
    const int g = lane >> 2, t = lane & 3, w0 = wid * 16;
#pragma unroll
    for (int n8 = 0; n8 < 8; n8++)
#pragma unroll
        for (int q = 0; q < 4; q++) {
            const int c = n8 * 8 + 2 * t + (q & 1);
            const int w = w0 + g + ((q >> 1) << 3);
            const int off = rb + c * CS + w;
            const float v = acc[n8][q];
            scratch[off] = v;
            dst[off] = base[off] + v;
        }
}

__device__ __forceinline__ void emit_add2(float* dst, const float acc[8][4],
                                          int rb, int wid, int lane)
{
    const int g = lane >> 2, t = lane & 3, w0 = wid * 16;
#pragma unroll
    for (int n8 = 0; n8 < 8; n8++)
#pragma unroll
        for (int q = 0; q < 4; q++) {
            const int c = n8 * 8 + 2 * t + (q & 1);
            const int w = w0 + g + ((q >> 1) << 3);
            dst[rb + c * CS + w] += acc[n8][q];
        }
}

__global__ void __launch_bounds__(384, 1) attn_tc(
    const float* __restrict__ low1, const float* __restrict__ low2,
    const uint4* __restrict__ qkp, const u32* __restrict__ lv,
    float* __restrict__ r2l1s, float* __restrict__ l2r1s,
    float* __restrict__ outL, float* __restrict__ outR)
{
    extern __shared__ u32 sm[];
    const int h = blockIdx.x, b = blockIdx.y;
    const int tid = threadIdx.x, wid = tid >> 5, lane = tid & 31;
    const int rb = b * 64 * CS + h * WW;
    const int pixbase = (b * HH + h) * WW;
    const int vbase4 = b * 64 * 4608 + h * 24;
    const u32 smem_base = (u32)__cvta_generic_to_shared(sm);
    const uint4* l1vh = (const uint4*)(lv + (size_t)0 * VPLANE);
    const uint4* l1vl = (const uint4*)(lv + (size_t)1 * VPLANE);
    const uint4* l2vh = (const uint4*)(lv + (size_t)2 * VPLANE);
    const uint4* l2vl = (const uint4*)(lv + (size_t)3 * VPLANE);
    float acc[8][4];

    // ---- stage 1: S1 = softmax(Q1^T K1) ----
    {
        uint4 vq[8], vk[8];
        qk_ldg(vq, vk, qkp + 0, qkp + (size_t)1 * NPIX * 16, pixbase, tid);
        qk_sts(sm, vq, vk, tid);
    }
    __syncthreads();
    compute_store_S(sm, smem_base, wid, lane);
    __syncthreads();

    // F = low2 (prepacked copy)
    {
        uint4 fa[4], fb[4];
        fv_ldg(fa, fb, l2vh, l2vl, vbase4, tid);
        fv_sts(sm, fa, fb, tid);
    }
    __syncthreads();
    apply_tc<false>(sm, smem_base, wid, lane, acc);
    __syncthreads();
    // overlap: load F=low1 while emitting outL
    {
        uint4 fa[4], fb[4];
        fv_ldg(fa, fb, l1vh, l1vl, vbase4, tid);
        emit_init2(outL, r2l1s, low1, acc, rb, wid, lane);
        fv_sts(sm, fa, fb, tid);
    }
    __syncthreads();
    apply_tc<true>(sm, smem_base, wid, lane, acc);
    __syncthreads();
    // overlap: stage Q2/K2 while emitting outR (QK/S region free after sync)
    {
        uint4 vq[8], vk[8];
        qk_ldg(vq, vk, qkp + (size_t)2 * NPIX * 16, qkp + (size_t)3 * NPIX * 16,
               pixbase, tid);
        emit_init2(outR, l2r1s, low2, acc, rb, wid, lane);
        qk_sts(sm, vq, vk, tid);
    }
    __syncthreads();

    // ---- stage 2: S2 = softmax(Q2^T K2) ----
    compute_store_S(sm, smem_base, wid, lane);
    __syncthreads();

    // F = low2 + l2r1
    {
        float4 f[8];
        f2_ldg(f, low2, l2r1s, rb, tid);
        f2_sts(sm, f, tid);
    }
    __syncthreads();
    apply_tc<false>(sm, smem_base, wid, lane, acc);
    __syncthreads();
    // overlap: load F=(low1+r2l1) while emitting outL
    {
        float4 f[8];
        f2_ldg(f, low1, r2l1s, rb, tid);
        emit_add2(outL, acc, rb, wid, lane);
        f2_sts(sm, f, tid);
    }
    __syncthreads();
    apply_tc<true>(sm, smem_base, wid, lane, acc);
    emit_add2(outR, acc, rb, wid, lane);
}

// =================================================================================
extern "C" void kernel_launch(void* const* d_in, const int* in_sizes, int n_in,
                              void* d_out, int out_size)
{
    const float* low1   = (const float*)d_in[0];
    const float* low2   = (const float*)d_in[1];
    const float* fe1_w1 = (const float*)d_in[2];
    const float* fe1_b1 = (const float*)d_in[3];
    const float* fe1_w2 = (const float*)d_in[4];
    const float* fe1_b2 = (const float*)d_in[5];
    const float* fe2_w1 = (const float*)d_in[6];
    const float* fe2_b1 = (const float*)d_in[7];
    const float* fe2_w2 = (const float*)d_in[8];
    const float* fe2_b2 = (const float*)d_in[9];
    const float* conv_w = (const float*)d_in[10];
    const float* conv_b = (const float*)d_in[11];
    float* out = (float*)d_out;

    uint4 *low1p, *low2p, *tp, *ap, *qkp, *wp;
    u32 *lv;
    float *r2l1, *l2r1;
    cudaGetSymbolAddress((void**)&low1p, g_low1p);
    cudaGetSymbolAddress((void**)&low2p, g_low2p);
    cudaGetSymbolAddress((void**)&tp,    g_tp);
    cudaGetSymbolAddress((void**)&ap,    g_ap);
    cudaGetSymbolAddress((void**)&qkp,   g_qkp);
    cudaGetSymbolAddress((void**)&wp,    g_wp);
    cudaGetSymbolAddress((void**)&lv,    g_lv);
    cudaGetSymbolAddress((void**)&r2l1,  g_r2l1);
    cudaGetSymbolAddress((void**)&l2r1,  g_l2r1);

    uint4* wp_fe1w1 = wp + 0 * 9216;
    uint4* wp_fe2w1 = wp + 1 * 9216;
    uint4* wp_fe1w2 = wp + 2 * 9216;
    uint4* wp_fe2w2 = wp + 3 * 9216;
    uint4* wp_convw = wp + 4 * 9216;

    cudaFuncSetAttribute(conv3x3_tc,
                         cudaFuncAttributeMaxDynamicSharedMemorySize,
                         CONV_SMEM_BYTES);
    cudaFuncSetAttribute(attn_tc,
                         cudaFuncAttributeMaxDynamicSharedMemorySize, ATTN_SMEM);

    const dim3 cgrid(WW / 16, HH / 16, 4 * BB);

    // single prep launch: weights + NHWC features + v-pair features
    prep_all<<<(PREP_TOTAL + 255) / 256, 256>>>(
        low1, low2, fe1_w1, fe2_w1, fe1_w2, fe2_w2, conv_w,
        low1p, low2p, lv, wp);

    conv3x3_tc<<<cgrid, 256, CONV_SMEM_BYTES>>>(
        low1p, low2p, 0, wp_fe1w1, wp_fe2w1, fe1_b1, fe2_b1,
        nullptr, nullptr, tp, 1);
    conv3x3_tc<<<cgrid, 256, CONV_SMEM_BYTES>>>(
        tp, tp, NPIX * 16, wp_fe1w2, wp_fe2w2, fe1_b2, fe2_b2,
        low1, low2, ap, 2);
    conv3x3_tc<<<cgrid, 256, CONV_SMEM_BYTES>>>(
        ap, ap, NPIX * 16, wp_convw, wp_convw, conv_b, conv_b,
        nullptr, nullptr, qkp, 3);

    attn_tc<<<dim3(HH, BB), 384, ATTN_SMEM>>>(
        low1, low2, qkp, lv, r2l1, l2r1, out, out + NT);
}

// round 16
// speedup vs baseline: 1.0144x; 1.0144x over previous
#include <cuda_runtime.h>
#include <cuda_bf16.h>

typedef unsigned int u32;
typedef unsigned long long u64;

// Problem constants
#define BB 4
#define CC 64
#define HH 192
#define WW 192
#define CS (HH*WW)            // channel stride = 36864
#define NT (BB*CC*HH*WW)      // elems per [B,C,H,W] fp32 tensor
#define NPIX (BB*HH*WW)       // pixels per tensor = 147456
#define VPLANE 4718592        // u32 per v-pair plane: 4*64*192*96

// ---------------- static scratch (no runtime allocation allowed) ----------------
__device__ uint4 g_low1p[NPIX * 16];
__device__ uint4 g_low2p[NPIX * 16];
__device__ uint4 g_tp[4 * NPIX * 16];   // packed conv1 outputs, per combo
__device__ uint4 g_ap[4 * NPIX * 16];   // packed conv2 outputs, per combo
__device__ uint4 g_qkp[4 * NPIX * 16];  // packed conv3 outputs: Q1,K1,Q2,K2
__device__ uint4 g_wp[5][9216];         // prepacked weights
__device__ u32   g_lv[2][2][VPLANE];    // v-pair packed low1/low2: [tensor][hi/lo]
__device__ float g_r2l1[NT];
__device__ float g_l2r1[NT];

// ---------------- helpers ----------------
__device__ __forceinline__ void split_pack(float ev, float ov, u32 &hi, u32 &lo)
{
    __nv_bfloat16 eh = __float2bfloat16(ev);
    __nv_bfloat16 oh = __float2bfloat16(ov);
    __nv_bfloat16 el = __float2bfloat16(ev - __bfloat162float(eh));
    __nv_bfloat16 ol = __float2bfloat16(ov - __bfloat162float(oh));
    hi = (u32)__bfloat16_as_ushort(eh) | ((u32)__bfloat16_as_ushort(oh) << 16);
    lo = (u32)__bfloat16_as_ushort(el) | ((u32)__bfloat16_as_ushort(ol) << 16);
}

__device__ __forceinline__ void mma16816(float c[4],
                                         u32 a0, u32 a1, u32 a2, u32 a3,
                                         u32 b0, u32 b1)
{
    asm volatile(
        "mma.sync.aligned.m16n8k16.row.col.f32.bf16.bf16.f32 "
        "{%0,%1,%2,%3}, {%4,%5,%6,%7}, {%8,%9}, {%0,%1,%2,%3};"
        : "+f"(c[0]), "+f"(c[1]), "+f"(c[2]), "+f"(c[3])
        : "r"(a0), "r"(a1), "r"(a2), "r"(a3), "r"(b0), "r"(b1));
}

__device__ __forceinline__ void ldsm4(u32 f[4], u32 addr)
{
    asm volatile(
        "ldmatrix.sync.aligned.m8n8.x4.shared.b16 {%0,%1,%2,%3}, [%4];"
        : "=r"(f[0]), "=r"(f[1]), "=r"(f[2]), "=r"(f[3]) : "r"(addr));
}

__device__ __forceinline__ void ldsm4t(u32 f[4], u32 addr)
{
    asm volatile(
        "ldmatrix.sync.aligned.m8n8.x4.trans.shared.b16 {%0,%1,%2,%3}, [%4];"
        : "=r"(f[0]), "=r"(f[1]), "=r"(f[2]), "=r"(f[3]) : "r"(addr));
}

// =================================================================================
// Single merged prep kernel: weights + NHWC features + v-pair features
// =================================================================================
#define NH_ITEMS (2 * 16 * NPIX)            // uint4 items, NHWC part
#define VP_ITEMS (2 * (VPLANE / 4))         // uint4 items, v-pair part
#define WT_ITEMS (5 * 9216)                 // uint4 items, weights part
#define PREP_TOTAL (NH_ITEMS + VP_ITEMS + WT_ITEMS)

__global__ void prep_all(const float* __restrict__ x1,
                         const float* __restrict__ x2,
                         const float* __restrict__ w0, const float* __restrict__ w1,
                         const float* __restrict__ w2, const float* __restrict__ w3,
                         const float* __restrict__ w4,
                         uint4* __restrict__ xp1, uint4* __restrict__ xp2,
                         u32* __restrict__ lv, uint4* __restrict__ wp)
{
    int gi = blockIdx.x * 256 + threadIdx.x;
    if (gi < NH_ITEMS) {
        int tsel = gi / (16 * NPIX);
        int r = gi - tsel * 16 * NPIX;
        int j = r / NPIX;
        int p = r - j * NPIX;
        const float* x = tsel ? x2 : x1;
        uint4* xp = tsel ? xp2 : xp1;
        int b = p / (HH * WW);
        int pos = p - b * HH * WW;
        const float* src = x + (size_t)(b * 64 + 4 * j) * CS + pos;
        u32 h0, l0, h1, l1;
        split_pack(src[0], src[CS], h0, l0);
        split_pack(src[2 * CS], src[3 * CS], h1, l1);
        xp[(size_t)p * 16 + j] = make_uint4(h0, l0, h1, l1);
        return;
    }
    int vi = gi - NH_ITEMS;
    if (vi < VP_ITEMS) {
        const int PER = VPLANE / 4;
        int tsel = vi / PER;
        int r = vi - tsel * PER;             // (bch)*24 + q4
        int q4 = r % 24;
        int bch = r / 24;
        const float* x = tsel ? x2 : x1;
        const float* src = x + (size_t)bch * WW + q4 * 8;
        float4 f0 = *(const float4*)src;
        float4 f1 = *(const float4*)(src + 4);
        u32 h0, l0, h1, l1, h2, l2, h3, l3;
        split_pack(f0.x, f0.y, h0, l0);
        split_pack(f0.z, f0.w, h1, l1);
        split_pack(f1.x, f1.y, h2, l2);
        split_pack(f1.z, f1.w, h3, l3);
        uint4* hi = (uint4*)(lv + ((size_t)tsel * 2 + 0) * VPLANE);
        uint4* lo = (uint4*)(lv + ((size_t)tsel * 2 + 1) * VPLANE);
        hi[r] = make_uint4(h0, h1, h2, h3);
        lo[r] = make_uint4(l0, l1, l2, l3);
        return;
    }
    int wi = vi - VP_ITEMS;
    if (wi >= WT_ITEMS) return;
    int which = wi / 9216, r = wi % 9216;
    const float* w = (which == 0) ? w0 : (which == 1) ? w1 :
                     (which == 2) ? w2 : (which == 3) ? w3 : w4;
    int tap = r >> 10, rem = r & 1023;
    int chunk = rem >> 8, rem2 = rem & 255;
    int o = rem2 >> 2, t = rem2 & 3;
    int c2a = chunk * 8 + t, c2b = c2a + 4;
    u32 h0, l0, h1, l1;
    split_pack(__ldg(&w[o * 576 + (2 * c2a) * 9 + tap]),
               __ldg(&w[o * 576 + (2 * c2a + 1) * 9 + tap]), h0, l0);
    split_pack(__ldg(&w[o * 576 + (2 * c2b) * 9 + tap]),
               __ldg(&w[o * 576 + (2 * c2b + 1) * 9 + tap]), h1, l1);
    wp[wi] = make_uint4(h0, h1, l0, l1);
}

// =================================================================================
// Tensor-core conv 3x3 (best config; bias pre-loaded into accumulators).
// =================================================================================
#define CONV_SMEM_BYTES (23040*4)

__global__ void __launch_bounds__(256, 2) conv3x3_tc(
    const uint4* __restrict__ xpA, const uint4* __restrict__ xpB, int xstride_u4,
    const uint4* __restrict__ wpA, const uint4* __restrict__ wpB,
    const float* __restrict__ bsA, const float* __restrict__ bsB,
    const float* __restrict__ skA, const float* __restrict__ skB,
    uint4* __restrict__ yp, int mode)
{
    extern __shared__ u32 smc[];
    u32* Hhi = smc;
    u32* Hlo = smc + 11520;

    const int bz = blockIdx.z;
    const int combo = bz >> 2, b = bz & 3;
    const uint4* xp = ((combo & 1) ? xpB : xpA) + (size_t)combo * xstride_u4;
    const uint4* wp = (combo >> 1) ? wpB : wpA;
    const float* bias = (combo >> 1) ? bsB : bsA;
    const float* skip = (combo & 1) ? skB : skA;

    const int ty = blockIdx.y, tx = blockIdx.x;
    const int tid = threadIdx.x, wid = tid >> 5, lane = tid & 31;
    const int g = lane >> 2, t = lane & 3;
    const int wr = wid & 3, wh = wid >> 2;

    float bv[4][2];
#pragma unroll
    for (int n8l = 0; n8l < 4; n8l++) {
        const int och0 = (wh * 4 + n8l) * 8 + 2 * t;
        bv[n8l][0] = __ldg(&bias[och0]);
        bv[n8l][1] = __ldg(&bias[och0 + 1]);
    }

    const int y0 = ty * 16 - 1, x0 = tx * 16 - 1;
    for (int i = tid; i < 324 * 16; i += 256) {
        int pix = i >> 4, j = i & 15;
        int yy = pix / 18, xx = pix - yy * 18;
        int gy = y0 + yy, gx = x0 + xx;
        uint4 v = make_uint4(0u, 0u, 0u, 0u);
        if (gy >= 0 && gy < HH && gx >= 0 && gx < WW)
            v = __ldg(&xp[(size_t)((b * HH + gy) * WW + gx) * 16 + j]);
        int unitoff = (yy * 20 + xx) * 32 + (((j >> 1) ^ (xx & 7)) << 2) + ((j & 1) << 1);
        *(uint2*)&Hhi[unitoff] = make_uint2(v.x, v.z);
        *(uint2*)&Hlo[unitoff] = make_uint2(v.y, v.w);
    }
    __syncthreads();

    float acc[4][4][4];
#pragma unroll
    for (int mi = 0; mi < 4; mi++)
#pragma unroll
        for (int n8 = 0; n8 < 4; n8++)
#pragma unroll
            for (int q = 0; q < 4; q++) acc[mi][n8][q] = bv[n8][q & 1];

    const int row0 = 4 * wr;
    const u32 hbase = (u32)__cvta_generic_to_shared(Hhi);
    const u32 lbase = (u32)__cvta_generic_to_shared(Hlo);
    const int m = lane & 15, half = lane >> 4;

    for (int ch = 0; ch < 4; ch++) {
#pragma unroll
        for (int dx = 0; dx < 3; dx++) {
            const int xm = dx + m;
            const int coff = (((ch * 2 + half) ^ (xm & 7)) << 4);
            const u32 a0 = (u32)((row0 * 20 + xm) * 128 + coff);
            u32 fh[6][4], fl[6][4];
#pragma unroll
            for (int ri = 0; ri < 6; ri++) {
                ldsm4(fh[ri], hbase + a0 + ri * 2560);
                ldsm4(fl[ri], lbase + a0 + ri * 2560);
            }
#pragma unroll
            for (int dy = 0; dy < 3; dy++) {
                const uint4* wrow = wp + (((dy * 3 + dx) * 4 + ch) * 64) * 4 + t;
                uint4 Bnext = __ldg(&wrow[((wh * 4) * 8 + g) * 4]);
#pragma unroll
                for (int n8l = 0; n8l < 4; n8l++) {
                    const uint4 Bc = Bnext;
                    if (n8l < 3)
                        Bnext = __ldg(&wrow[(((wh * 4 + n8l + 1)) * 8 + g) * 4]);
#pragma unroll
                    for (int mi = 0; mi < 4; mi++) {
                        const int ri = mi + dy;
                        mma16816(acc[mi][n8l], fh[ri][0], fh[ri][1], fh[ri][2], fh[ri][3], Bc.x, Bc.y);
                    }
#pragma unroll
                    for (int mi = 0; mi < 4; mi++) {
                        const int ri = mi + dy;
                        mma16816(acc[mi][n8l], fh[ri][0], fh[ri][1], fh[ri][2], fh[ri][3], Bc.z, Bc.w);
                    }
#pragma unroll
                    for (int mi = 0; mi < 4; mi++) {
                        const int ri = mi + dy;
                        mma16816(acc[mi][n8l], fl[ri][0], fl[ri][1], fl[ri][2], fl[ri][3], Bc.x, Bc.y);
                    }
                }
            }
        }
    }

    const int gyb = ty * 16 + row0, gxb = tx * 16;
    uint2* ypc = (uint2*)(yp + (size_t)combo * (NPIX * 16));
#pragma unroll
    for (int n8l = 0; n8l < 4; n8l++) {
        const int n8g = wh * 4 + n8l;
        const int och0 = n8g * 8 + 2 * t;
        const int c2o = n8g * 4 + t;
#pragma unroll
        for (int mi = 0; mi < 4; mi++) {
            const int gy = gyb + mi;
#pragma unroll
            for (int hlf = 0; hlf < 2; hlf++) {
                const int px = gxb + g + hlf * 8;
                float v0 = acc[mi][n8l][hlf * 2 + 0];
                float v1 = acc[mi][n8l][hlf * 2 + 1];
                if (mode == 1) {
                    v0 = fmaxf(v0, 0.f);
                    v1 = fmaxf(v1, 0.f);
                } else if (mode == 2) {
                    const int off = ((b * 64 + och0) * HH + gy) * WW + px;
                    v0 += __ldg(&skip[off]);
                    v1 += __ldg(&skip[off + CS]);
                }
                u32 h, l;
                split_pack(v0, v1, h, l);
                ypc[(size_t)((b * HH + gy) * WW + px) * 32 + c2o] = make_uint2(h, l);
            }
        }
    }
}

// =================================================================================
// Tensor-core attention (best-measured config + stage-2 F reuse: outR holds
// low2+l2r1 and outL holds low1+r2l1 after stage-1 emits, so stage-2 F staging
// reads ONE array per phase; outL is loaded to regs and barrier-separated from
// its own emit_add2 to avoid the intra-CTA W/R race).
// =================================================================================
#define SL_B   73728
#define QSH_U  0
#define QSL_U  6144
#define KH_U   12288
#define KL_U   19200
#define FH_U   36864
#define FL_U   43264
#define ATTN_SMEM 198656

__device__ __forceinline__ void qk_ldg(uint4 vq[8], uint4 vk[8],
                                       const uint4* __restrict__ q,
                                       const uint4* __restrict__ k,
                                       int pixbase, int tid)
{
#pragma unroll
    for (int it = 0; it < 8; it++) {
        int i = tid + it * 384;
        int p = i >> 4, j = i & 15;
        vq[it] = __ldg(&q[(size_t)(pixbase + p) * 16 + j]);
        vk[it] = __ldg(&k[(size_t)(pixbase + p) * 16 + j]);
    }
}

__device__ __forceinline__ void qk_sts(u32* sm, const uint4 vq[8],
                                       const uint4 vk[8], int tid)
{
#pragma unroll
    for (int it = 0; it < 8; it++) {
        int i = tid + it * 384;
        int p = i >> 4, j = i & 15;
        int us = (j >> 1) ^ (p & 7);
        int qoff = p * 32 + us * 4 + (j & 1) * 2;
        *(uint2*)(sm + QSH_U + qoff) = make_uint2(vq[it].x, vq[it].z);
        *(uint2*)(sm + QSL_U + qoff) = make_uint2(vq[it].y, vq[it].w);
        int koff = p * 36 + 2 * j;
        *(uint2*)(sm + KH_U + koff) = make_uint2(vk[it].x, vk[it].z);
        *(uint2*)(sm + KL_U + koff) = make_uint2(vk[it].y, vk[it].w);
    }
}

__device__ __forceinline__ void compute_store_S(u32* sm, u32 smem_base,
                                                int wid, int lane)
{
    const int g = lane >> 2, t = lane & 3;
    const int w0 = wid * 16;
    const int tile = lane >> 3, lr = lane & 7;
    const int arow = w0 + lr + ((tile & 1) << 3);

    float acc[24][4];
#pragma unroll
    for (int n8 = 0; n8 < 24; n8++)
#pragma unroll
        for (int q = 0; q < 4; q++) acc[n8][q] = 0.f;

    const u32* kh = sm + KH_U;
    const u32* kl = sm + KL_U;

#pragma unroll
    for (int ch = 0; ch < 4; ch++) {
        const int ut = 2 * ch + (tile >> 1);
        const int us = ut ^ (arow & 7);
        const u32 qaddr = smem_base + (u32)(arow * 128 + us * 16);
        u32 ah[4], al[4];
        ldsm4(ah, qaddr);
        ldsm4(al, qaddr + 24576);
        const int kbase = ch * 8 + t;
#pragma unroll
        for (int n8 = 0; n8 < 24; n8++) {
            const int p36 = (n8 * 8 + g) * 36;
            u32 b0h = kh[p36 + kbase], b1h = kh[p36 + kbase + 4];
            u32 b0l = kl[p36 + kbase], b1l = kl[p36 + kbase + 4];
            mma16816(acc[n8], ah[0], ah[1], ah[2], ah[3], b0h, b1h);
            mma16816(acc[n8], ah[0], ah[1], ah[2], ah[3], b0l, b1l);
            mma16816(acc[n8], al[0], al[1], al[2], al[3], b0h, b1h);
        }
    }

    float m0 = -1e30f, m1 = -1e30f;
#pragma unroll
    for (int n8 = 0; n8 < 24; n8++) {
        m0 = fmaxf(m0, fmaxf(acc[n8][0], acc[n8][1]));
        m1 = fmaxf(m1, fmaxf(acc[n8][2], acc[n8][3]));
    }
    m0 = fmaxf(m0, __shfl_xor_sync(0xffffffffu, m0, 1));
    m0 = fmaxf(m0, __shfl_xor_sync(0xffffffffu, m0, 2));
    m1 = fmaxf(m1, __shfl_xor_sync(0xffffffffu, m1, 1));
    m1 = fmaxf(m1, __shfl_xor_sync(0xffffffffu, m1, 2));
    float s0 = 0.f, s1 = 0.f;
#pragma unroll
    for (int n8 = 0; n8 < 24; n8++) {
        acc[n8][0] = __expf(acc[n8][0] - m0);
        acc[n8][1] = __expf(acc[n8][1] - m0);
        acc[n8][2] = __expf(acc[n8][2] - m1);
        acc[n8][3] = __expf(acc[n8][3] - m1);
        s0 += acc[n8][0] + acc[n8][1];
        s1 += acc[n8][2] + acc[n8][3];
    }
    s0 += __shfl_xor_sync(0xffffffffu, s0, 1);
    s0 += __shfl_xor_sync(0xffffffffu, s0, 2);
    s1 += __shfl_xor_sync(0xffffffffu, s1, 1);
    s1 += __shfl_xor_sync(0xffffffffu, s1, 2);
    const float inv0 = 1.0f / s0, inv1 = 1.0f / s1;

    __syncthreads();   // all warps done reading Qs/Ks before S overwrites them

    u32* shp = sm;
    u32* slp = sm + SL_B / 4;
    const int rg = w0 + g;
#pragma unroll
    for (int n8 = 0; n8 < 24; n8++) {
        const int us = (n8 & 24) | ((n8 & 7) ^ (rg & 7));
        const int off = us * 4 + t;
        u32 h, l;
        split_pack(acc[n8][0] * inv0, acc[n8][1] * inv0, h, l);
        shp[rg * 96 + off] = h;
        slp[rg * 96 + off] = l;
        split_pack(acc[n8][2] * inv1, acc[n8][3] * inv1, h, l);
        shp[(rg + 8) * 96 + off] = h;
        slp[(rg + 8) * 96 + off] = l;
    }
}

// ---- v-pair F loads (prepacked; pure copy) ----
__device__ __forceinline__ void fv_ldg(uint4 fa[4], uint4 fb[4],
                                       const uint4* __restrict__ vh,
                                       const uint4* __restrict__ vl,
                                       int vbase4, int tid)
{
#pragma unroll
    for (int it = 0; it < 4; it++) {
        int i4 = tid + it * 384;
        int c = i4 / 24, q4 = i4 - c * 24;
        fa[it] = __ldg(&vh[vbase4 + c * 4608 + q4]);
        fb[it] = __ldg(&vl[vbase4 + c * 4608 + q4]);
    }
}

__device__ __forceinline__ void fv_sts(u32* sm, const uint4 fa[4],
                                       const uint4 fb[4], int tid)
{
#pragma unroll
    for (int it = 0; it < 4; it++) {
        int i4 = tid + it * 384;
        int c = i4 / 24, q4 = i4 - c * 24;
        *(uint4*)(sm + FH_U + c * 100 + q4 * 4) = fa[it];
        *(uint4*)(sm + FL_U + c * 100 + q4 * 4) = fb[it];
    }
}

// ---- fp32 single-source F load (stage-2 fused applies read outR / outL) ----
__device__ __forceinline__ void f1_ldg(float4 f[8], const float* __restrict__ s,
                                       int rb, int tid)
{
#pragma unroll
    for (int it = 0; it < 8; it++) {
        int i = tid + it * 384;
        int c = i / 48, q = i - c * 48;
        f[it] = *(const float4*)(s + rb + c * CS + q * 4);
    }
}

__device__ __forceinline__ void f1_sts(u32* sm, const float4 f[8], int tid)
{
#pragma unroll
    for (int it = 0; it < 8; it++) {
        int i = tid + it * 384;
        int c = i / 48, q = i - c * 48;
        u32 h0, l0, h1, l1;
        split_pack(f[it].x, f[it].y, h0, l0);
        split_pack(f[it].z, f[it].w, h1, l1);
        *(uint2*)(sm + FH_U + c * 100 + 2 * q) = make_uint2(h0, h1);
        *(uint2*)(sm + FL_U + c * 100 + 2 * q) = make_uint2(l0, l1);
    }
}

template <bool TR>
__device__ __forceinline__ void apply_tc(u32* sm, u32 smem_base,
                                         int wid, int lane, float acc[8][4])
{
    const int g = lane >> 2, t = lane & 3;
    const int w0 = wid * 16;
    const int tile = lane >> 3, lr = lane & 7;
    const u32* fh = sm + FH_U;
    const u32* fl = sm + FL_U;

#pragma unroll
    for (int n8 = 0; n8 < 8; n8++)
#pragma unroll
        for (int q = 0; q < 4; q++) acc[n8][q] = 0.f;

#pragma unroll
    for (int k = 0; k < 12; k++) {
        u32 ah[4], al[4];
        if (!TR) {
            const int row = w0 + lr + ((tile & 1) << 3);
            const int ut = 2 * k + (tile >> 1);
            const int us = (ut & 24) | ((ut & 7) ^ (row & 7));
            const u32 addr = smem_base + (u32)(row * 384 + us * 16);
            ldsm4(ah, addr);
            ldsm4(al, addr + 73728);
        } else {
            const int srow = k * 16 + lr + ((tile >> 1) << 3);
            const int cu = 2 * wid + (tile & 1);
            const int us = (cu & 24) | ((cu & 7) ^ (srow & 7));
            const u32 addr = smem_base + (u32)(srow * 384 + us * 16);
            ldsm4t(ah, addr);
            ldsm4t(al, addr + 73728);
        }
        const int fb = 8 * k + t;
#pragma unroll
        for (int n8 = 0; n8 < 8; n8++) {
            const int c100 = (n8 * 8 + g) * 100;
            u32 b0h = fh[c100 + fb], b1h = fh[c100 + fb + 4];
            u32 b0l = fl[c100 + fb], b1l = fl[c100 + fb + 4];
            mma16816(acc[n8], ah[0], ah[1], ah[2], ah[3], b0h, b1h);
            mma16816(acc[n8], ah[0], ah[1], ah[2], ah[3], b0l, b1l);
            mma16816(acc[n8], al[0], al[1], al[2], al[3], b0h, b1h);
        }
    }
}

__device__ __forceinline__ void emit_init2(float* dst, float* scratch,
                                           const float* base, const float acc[8][4],
                                           int rb, int wid, int lane)
{
    const int g = lane >> 2, t = lane & 3, w0 = wid * 16;
#pragma unroll
    for (int n8 = 0; n8 < 8; n8++)
#pragma unroll
        for (int q = 0; q < 4; q++) {
            const int c = n8 * 8 + 2 * t + (q & 1);
            const int w = w0 + g + ((q >> 1) << 3);
            const int off = rb + c * CS + w;
            const float v = acc[n8][q];
            scratch[off] = v;
            dst[off] = base[off] + v;
        }
}

__device__ __forceinline__ void emit_add2(float* dst, const float acc[8][4],
                                          int rb, int wid, int lane)
{
    const int g = lane >> 2, t = lane & 3, w0 = wid * 16;
#pragma unroll
    for (int n8 = 0; n8 < 8; n8++)
#pragma unroll
        for (int q = 0; q < 4; q++) {
            const int c = n8 * 8 + 2 * t + (q & 1);
            const int w = w0 + g + ((q >> 1) << 3);
            dst[rb + c * CS + w] += acc[n8][q];
        }
}

__global__ void __launch_bounds__(384, 1) attn_tc(
    const float* __restrict__ low1, const float* __restrict__ low2,
    const uint4* __restrict__ qkp, const u32* __restrict__ lv,
    float* __restrict__ r2l1s, float* __restrict__ l2r1s,
    float* __restrict__ outL, float* __restrict__ outR)
{
    extern __shared__ u32 sm[];
    const int h = blockIdx.x, b = blockIdx.y;
    const int tid = threadIdx.x, wid = tid >> 5, lane = tid & 31;
    const int rb = b * 64 * CS + h * WW;
    const int pixbase = (b * HH + h) * WW;
    const int vbase4 = b * 64 * 4608 + h * 24;
    const u32 smem_base = (u32)__cvta_generic_to_shared(sm);
    const uint4* l1vh = (const uint4*)(lv + (size_t)0 * VPLANE);
    const uint4* l1vl = (const uint4*)(lv + (size_t)1 * VPLANE);
    const uint4* l2vh = (const uint4*)(lv + (size_t)2 * VPLANE);
    const uint4* l2vl = (const uint4*)(lv + (size_t)3 * VPLANE);
    float acc[8][4];

    // ---- stage 1: S1 = softmax(Q1^T K1) ----
    {
        uint4 vq[8], vk[8];
        qk_ldg(vq, vk, qkp + 0, qkp + (size_t)1 * NPIX * 16, pixbase, tid);
        qk_sts(sm, vq, vk, tid);
    }
    __syncthreads();
    compute_store_S(sm, smem_base, wid, lane);
    __syncthreads();

    // F = low2 (prepacked copy)
    {
        uint4 fa[4], fb[4];
        fv_ldg(fa, fb, l2vh, l2vl, vbase4, tid);
        fv_sts(sm, fa, fb, tid);
    }
    __syncthreads();
    apply_tc<false>(sm, smem_base, wid, lane, acc);
    __syncthreads();
    // overlap: load F=low1 while emitting outL (= low1 + r2l1 after this emit)
    {
        uint4 fa[4], fb[4];
        fv_ldg(fa, fb, l1vh, l1vl, vbase4, tid);
        emit_init2(outL, r2l1s, low1, acc, rb, wid, lane);
        fv_sts(sm, fa, fb, tid);
    }
    __syncthreads();
    apply_tc<true>(sm, smem_base, wid, lane, acc);
    __syncthreads();
    // overlap: stage Q2/K2 while emitting outR (= low2 + l2r1 after this emit)
    {
        uint4 vq[8], vk[8];
        qk_ldg(vq, vk, qkp + (size_t)2 * NPIX * 16, qkp + (size_t)3 * NPIX * 16,
               pixbase, tid);
        emit_init2(outR, l2r1s, low2, acc, rb, wid, lane);
        qk_sts(sm, vq, vk, tid);
    }
    __syncthreads();

    // ---- stage 2: S2 = softmax(Q2^T K2) ----
    compute_store_S(sm, smem_base, wid, lane);
    __syncthreads();

    // F = low2 + l2r1 == current outR (single-array read)
    {
        float4 f[8];
        f1_ldg(f, outR, rb, tid);
        f1_sts(sm, f, tid);
    }
    __syncthreads();
    apply_tc<false>(sm, smem_base, wid, lane, acc);
    __syncthreads();
    // F = low1 + r2l1 == current outL; must be fully read BEFORE emit_add2(outL)
    {
        float4 f[8];
        f1_ldg(f, outL, rb, tid);
        __syncthreads();                 // all outL reads complete before writes
        emit_add2(outL, acc, rb, wid, lane);
        f1_sts(sm, f, tid);
    }
    __syncthreads();
    apply_tc<true>(sm, smem_base, wid, lane, acc);
    emit_add2(outR, acc, rb, wid, lane);
}

// =================================================================================
extern "C" void kernel_launch(void* const* d_in, const int* in_sizes, int n_in,
                              void* d_out, int out_size)
{
    const float* low1   = (const float*)d_in[0];
    const float* low2   = (const float*)d_in[1];
    const float* fe1_w1 = (const float*)d_in[2];
    const float* fe1_b1 = (const float*)d_in[3];
    const float* fe1_w2 = (const float*)d_in[4];
    const float* fe1_b2 = (const float*)d_in[5];
    const float* fe2_w1 = (const float*)d_in[6];
    const float* fe2_b1 = (const float*)d_in[7];
    const float* fe2_w2 = (const float*)d_in[8];
    const float* fe2_b2 = (const float*)d_in[9];
    const float* conv_w = (const float*)d_in[10];
    const float* conv_b = (const float*)d_in[11];
    float* out = (float*)d_out;

    uint4 *low1p, *low2p, *tp, *ap, *qkp, *wp;
    u32 *lv;
    float *r2l1, *l2r1;
    cudaGetSymbolAddress((void**)&low1p, g_low1p);
    cudaGetSymbolAddress((void**)&low2p, g_low2p);
    cudaGetSymbolAddress((void**)&tp,    g_tp);
    cudaGetSymbolAddress((void**)&ap,    g_ap);
    cudaGetSymbolAddress((void**)&qkp,   g_qkp);
    cudaGetSymbolAddress((void**)&wp,    g_wp);
    cudaGetSymbolAddress((void**)&lv,    g_lv);
    cudaGetSymbolAddress((void**)&r2l1,  g_r2l1);
    cudaGetSymbolAddress((void**)&l2r1,  g_l2r1);

    uint4* wp_fe1w1 = wp + 0 * 9216;
    uint4* wp_fe2w1 = wp + 1 * 9216;
    uint4* wp_fe1w2 = wp + 2 * 9216;
    uint4* wp_fe2w2 = wp + 3 * 9216;
    uint4* wp_convw = wp + 4 * 9216;

    cudaFuncSetAttribute(conv3x3_tc,
                         cudaFuncAttributeMaxDynamicSharedMemorySize,
                         CONV_SMEM_BYTES);
    cudaFuncSetAttribute(attn_tc,
                         cudaFuncAttributeMaxDynamicSharedMemorySize, ATTN_SMEM);

    const dim3 cgrid(WW / 16, HH / 16, 4 * BB);

    // single prep launch: weights + NHWC features + v-pair features
    prep_all<<<(PREP_TOTAL + 255) / 256, 256>>>(
        low1, low2, fe1_w1, fe2_w1, fe1_w2, fe2_w2, conv_w,
        low1p, low2p, lv, wp);

    conv3x3_tc<<<cgrid, 256, CONV_SMEM_BYTES>>>(
        low1p, low2p, 0, wp_fe1w1, wp_fe2w1, fe1_b1, fe2_b1,
        nullptr, nullptr, tp, 1);
    conv3x3_tc<<<cgrid, 256, CONV_SMEM_BYTES>>>(
        tp, tp, NPIX * 16, wp_fe1w2, wp_fe2w2, fe1_b2, fe2_b2,
        low1, low2, ap, 2);
    conv3x3_tc<<<cgrid, 256, CONV_SMEM_BYTES>>>(
        ap, ap, NPIX * 16, wp_convw, wp_convw, conv_b, conv_b,
        nullptr, nullptr, qkp, 3);

    attn_tc<<<dim3(HH, BB), 384, ATTN_SMEM>>>(
        low1, low2, qkp, lv, r2l1, l2r1, out, out + NT);
}

// round 17
// speedup vs baseline: 1.0397x; 1.0249x over previous
#include <cuda_runtime.h>
#include <cuda_bf16.h>

typedef unsigned int u32;
typedef unsigned long long u64;

// Problem constants
#define BB 4
#define CC 64
#define HH 192
#define WW 192
#define CS (HH*WW)            // channel stride = 36864
#define NT (BB*CC*HH*WW)      // elems per [B,C,H,W] fp32 tensor
#define NPIX (BB*HH*WW)       // pixels per tensor = 147456
#define VPLANE 4718592        // u32 per v-pair plane: 4*64*192*96

// ---------------- static scratch (no runtime allocation allowed) ----------------
__device__ uint4 g_low1p[NPIX * 16];
__device__ uint4 g_low2p[NPIX * 16];
__device__ uint4 g_tp[4 * NPIX * 16];   // packed conv1 outputs, per combo
__device__ uint4 g_ap[4 * NPIX * 16];   // packed conv2 outputs, per combo
__device__ uint4 g_qkp[4 * NPIX * 16];  // packed conv3 outputs: Q1,K1,Q2,K2
__device__ uint4 g_wp[5][9216];         // prepacked weights
__device__ u32   g_lv[2][2][VPLANE];    // v-pair packed low1/low2: [tensor][hi/lo]

// ---------------- helpers ----------------
__device__ __forceinline__ void split_pack(float ev, float ov, u32 &hi, u32 &lo)
{
    __nv_bfloat16 eh = __float2bfloat16(ev);
    __nv_bfloat16 oh = __float2bfloat16(ov);
    __nv_bfloat16 el = __float2bfloat16(ev - __bfloat162float(eh));
    __nv_bfloat16 ol = __float2bfloat16(ov - __bfloat162float(oh));
    hi = (u32)__bfloat16_as_ushort(eh) | ((u32)__bfloat16_as_ushort(oh) << 16);
    lo = (u32)__bfloat16_as_ushort(el) | ((u32)__bfloat16_as_ushort(ol) << 16);
}

__device__ __forceinline__ void mma16816(float c[4],
                                         u32 a0, u32 a1, u32 a2, u32 a3,
                                         u32 b0, u32 b1)
{
    asm volatile(
        "mma.sync.aligned.m16n8k16.row.col.f32.bf16.bf16.f32 "
        "{%0,%1,%2,%3}, {%4,%5,%6,%7}, {%8,%9}, {%0,%1,%2,%3};"
        : "+f"(c[0]), "+f"(c[1]), "+f"(c[2]), "+f"(c[3])
        : "r"(a0), "r"(a1), "r"(a2), "r"(a3), "r"(b0), "r"(b1));
}

__device__ __forceinline__ void ldsm4(u32 f[4], u32 addr)
{
    asm volatile(
        "ldmatrix.sync.aligned.m8n8.x4.shared.b16 {%0,%1,%2,%3}, [%4];"
        : "=r"(f[0]), "=r"(f[1]), "=r"(f[2]), "=r"(f[3]) : "r"(addr));
}

__device__ __forceinline__ void ldsm4t(u32 f[4], u32 addr)
{
    asm volatile(
        "ldmatrix.sync.aligned.m8n8.x4.trans.shared.b16 {%0,%1,%2,%3}, [%4];"
        : "=r"(f[0]), "=r"(f[1]), "=r"(f[2]), "=r"(f[3]) : "r"(addr));
}

// =================================================================================
// Single merged prep kernel: weights + NHWC features + v-pair features
// =================================================================================
#define NH_ITEMS (2 * 16 * NPIX)            // uint4 items, NHWC part
#define VP_ITEMS (2 * (VPLANE / 4))         // uint4 items, v-pair part
#define WT_ITEMS (5 * 9216)                 // uint4 items, weights part
#define PREP_TOTAL (NH_ITEMS + VP_ITEMS + WT_ITEMS)

__global__ void prep_all(const float* __restrict__ x1,
                         const float* __restrict__ x2,
                         const float* __restrict__ w0, const float* __restrict__ w1,
                         const float* __restrict__ w2, const float* __restrict__ w3,
                         const float* __restrict__ w4,
                         uint4* __restrict__ xp1, uint4* __restrict__ xp2,
                         u32* __restrict__ lv, uint4* __restrict__ wp)
{
    int gi = blockIdx.x * 256 + threadIdx.x;
    if (gi < NH_ITEMS) {
        int tsel = gi / (16 * NPIX);
        int r = gi - tsel * 16 * NPIX;
        int j = r / NPIX;
        int p = r - j * NPIX;
        const float* x = tsel ? x2 : x1;
        uint4* xp = tsel ? xp2 : xp1;
        int b = p / (HH * WW);
        int pos = p - b * HH * WW;
        const float* src = x + (size_t)(b * 64 + 4 * j) * CS + pos;
        u32 h0, l0, h1, l1;
        split_pack(src[0], src[CS], h0, l0);
        split_pack(src[2 * CS], src[3 * CS], h1, l1);
        xp[(size_t)p * 16 + j] = make_uint4(h0, l0, h1, l1);
        return;
    }
    int vi = gi - NH_ITEMS;
    if (vi < VP_ITEMS) {
        const int PER = VPLANE / 4;
        int tsel = vi / PER;
        int r = vi - tsel * PER;             // (bch)*24 + q4
        int q4 = r % 24;
        int bch = r / 24;
        const float* x = tsel ? x2 : x1;
        const float* src = x + (size_t)bch * WW + q4 * 8;
        float4 f0 = *(const float4*)src;
        float4 f1 = *(const float4*)(src + 4);
        u32 h0, l0, h1, l1, h2, l2, h3, l3;
        split_pack(f0.x, f0.y, h0, l0);
        split_pack(f0.z, f0.w, h1, l1);
        split_pack(f1.x, f1.y, h2, l2);
        split_pack(f1.z, f1.w, h3, l3);
        uint4* hi = (uint4*)(lv + ((size_t)tsel * 2 + 0) * VPLANE);
        uint4* lo = (uint4*)(lv + ((size_t)tsel * 2 + 1) * VPLANE);
        hi[r] = make_uint4(h0, h1, h2, h3);
        lo[r] = make_uint4(l0, l1, l2, l3);
        return;
    }
    int wi = vi - VP_ITEMS;
    if (wi >= WT_ITEMS) return;
    int which = wi / 9216, r = wi % 9216;
    const float* w = (which == 0) ? w0 : (which == 1) ? w1 :
                     (which == 2) ? w2 : (which == 3) ? w3 : w4;
    int tap = r >> 10, rem = r & 1023;
    int chunk = rem >> 8, rem2 = rem & 255;
    int o = rem2 >> 2, t = rem2 & 3;
    int c2a = chunk * 8 + t, c2b = c2a + 4;
    u32 h0, l0, h1, l1;
    split_pack(__ldg(&w[o * 576 + (2 * c2a) * 9 + tap]),
               __ldg(&w[o * 576 + (2 * c2a + 1) * 9 + tap]), h0, l0);
    split_pack(__ldg(&w[o * 576 + (2 * c2b) * 9 + tap]),
               __ldg(&w[o * 576 + (2 * c2b + 1) * 9 + tap]), h1, l1);
    wp[wi] = make_uint4(h0, h1, l0, l1);
}

// =================================================================================
// Tensor-core conv 3x3 (best config; bias pre-loaded into accumulators).
// =================================================================================
#define CONV_SMEM_BYTES (23040*4)

__global__ void __launch_bounds__(256, 2) conv3x3_tc(
    const uint4* __restrict__ xpA, const uint4* __restrict__ xpB, int xstride_u4,
    const uint4* __restrict__ wpA, const uint4* __restrict__ wpB,
    const float* __restrict__ bsA, const float* __restrict__ bsB,
    const float* __restrict__ skA, const float* __restrict__ skB,
    uint4* __restrict__ yp, int mode)
{
    extern __shared__ u32 smc[];
    u32* Hhi = smc;
    u32* Hlo = smc + 11520;

    const int bz = blockIdx.z;
    const int combo = bz >> 2, b = bz & 3;
    const uint4* xp = ((combo & 1) ? xpB : xpA) + (size_t)combo * xstride_u4;
    const uint4* wp = (combo >> 1) ? wpB : wpA;
    const float* bias = (combo >> 1) ? bsB : bsA;
    const float* skip = (combo & 1) ? skB : skA;

    const int ty = blockIdx.y, tx = blockIdx.x;
    const int tid = threadIdx.x, wid = tid >> 5, lane = tid & 31;
    const int g = lane >> 2, t = lane & 3;
    const int wr = wid & 3, wh = wid >> 2;

    float bv[4][2];
#pragma unroll
    for (int n8l = 0; n8l < 4; n8l++) {
        const int och0 = (wh * 4 + n8l) * 8 + 2 * t;
        bv[n8l][0] = __ldg(&bias[och0]);
        bv[n8l][1] = __ldg(&bias[och0 + 1]);
    }

    const int y0 = ty * 16 - 1, x0 = tx * 16 - 1;
    for (int i = tid; i < 324 * 16; i += 256) {
        int pix = i >> 4, j = i & 15;
        int yy = pix / 18, xx = pix - yy * 18;
        int gy = y0 + yy, gx = x0 + xx;
        uint4 v = make_uint4(0u, 0u, 0u, 0u);
        if (gy >= 0 && gy < HH && gx >= 0 && gx < WW)
            v = __ldg(&xp[(size_t)((b * HH + gy) * WW + gx) * 16 + j]);
        int unitoff = (yy * 20 + xx) * 32 + (((j >> 1) ^ (xx & 7)) << 2) + ((j & 1) << 1);
        *(uint2*)&Hhi[unitoff] = make_uint2(v.x, v.z);
        *(uint2*)&Hlo[unitoff] = make_uint2(v.y, v.w);
    }
    __syncthreads();

    float acc[4][4][4];
#pragma unroll
    for (int mi = 0; mi < 4; mi++)
#pragma unroll
        for (int n8 = 0; n8 < 4; n8++)
#pragma unroll
            for (int q = 0; q < 4; q++) acc[mi][n8][q] = bv[n8][q & 1];

    const int row0 = 4 * wr;
    const u32 hbase = (u32)__cvta_generic_to_shared(Hhi);
    const u32 lbase = (u32)__cvta_generic_to_shared(Hlo);
    const int m = lane & 15, half = lane >> 4;

    for (int ch = 0; ch < 4; ch++) {
#pragma unroll
        for (int dx = 0; dx < 3; dx++) {
            const int xm = dx + m;
            const int coff = (((ch * 2 + half) ^ (xm & 7)) << 4);
            const u32 a0 = (u32)((row0 * 20 + xm) * 128 + coff);
            u32 fh[6][4], fl[6][4];
#pragma unroll
            for (int ri = 0; ri < 6; ri++) {
                ldsm4(fh[ri], hbase + a0 + ri * 2560);
                ldsm4(fl[ri], lbase + a0 + ri * 2560);
            }
#pragma unroll
            for (int dy = 0; dy < 3; dy++) {
                const uint4* wrow = wp + (((dy * 3 + dx) * 4 + ch) * 64) * 4 + t;
                uint4 Bnext = __ldg(&wrow[((wh * 4) * 8 + g) * 4]);
#pragma unroll
                for (int n8l = 0; n8l < 4; n8l++) {
                    const uint4 Bc = Bnext;
                    if (n8l < 3)
                        Bnext = __ldg(&wrow[(((wh * 4 + n8l + 1)) * 8 + g) * 4]);
#pragma unroll
                    for (int mi = 0; mi < 4; mi++) {
                        const int ri = mi + dy;
                        mma16816(acc[mi][n8l], fh[ri][0], fh[ri][1], fh[ri][2], fh[ri][3], Bc.x, Bc.y);
                    }
#pragma unroll
                    for (int mi = 0; mi < 4; mi++) {
                        const int ri = mi + dy;
                        mma16816(acc[mi][n8l], fh[ri][0], fh[ri][1], fh[ri][2], fh[ri][3], Bc.z, Bc.w);
                    }
#pragma unroll
                    for (int mi = 0; mi < 4; mi++) {
                        const int ri = mi + dy;
                        mma16816(acc[mi][n8l], fl[ri][0], fl[ri][1], fl[ri][2], fl[ri][3], Bc.x, Bc.y);
                    }
                }
            }
        }
    }

    const int gyb = ty * 16 + row0, gxb = tx * 16;
    uint2* ypc = (uint2*)(yp + (size_t)combo * (NPIX * 16));
#pragma unroll
    for (int n8l = 0; n8l < 4; n8l++) {
        const int n8g = wh * 4 + n8l;
        const int och0 = n8g * 8 + 2 * t;
        const int c2o = n8g * 4 + t;
#pragma unroll
        for (int mi = 0; mi < 4; mi++) {
            const int gy = gyb + mi;
#pragma unroll
            for (int hlf = 0; hlf < 2; hlf++) {
                const int px = gxb + g + hlf * 8;
                float v0 = acc[mi][n8l][hlf * 2 + 0];
                float v1 = acc[mi][n8l][hlf * 2 + 1];
                if (mode == 1) {
                    v0 = fmaxf(v0, 0.f);
                    v1 = fmaxf(v1, 0.f);
                } else if (mode == 2) {
                    const int off = ((b * 64 + och0) * HH + gy) * WW + px;
                    v0 += __ldg(&skip[off]);
                    v1 += __ldg(&skip[off + CS]);
                }
                u32 h, l;
                split_pack(v0, v1, h, l);
                ypc[(size_t)((b * HH + gy) * WW + px) * 32 + c2o] = make_uint2(h, l);
            }
        }
    }
}

// =================================================================================
// Tensor-core attention (R16 best config, dead scratch stores removed:
// stage-2 F inputs are read directly from outR / outL, so the r2l1/l2r1
// scratch arrays are gone entirely).
// =================================================================================
#define SL_B   73728
#define QSH_U  0
#define QSL_U  6144
#define KH_U   12288
#define KL_U   19200
#define FH_U   36864
#define FL_U   43264
#define ATTN_SMEM 198656

__device__ __forceinline__ void qk_ldg(uint4 vq[8], uint4 vk[8],
                                       const uint4* __restrict__ q,
                                       const uint4* __restrict__ k,
                                       int pixbase, int tid)
{
#pragma unroll
    for (int it = 0; it < 8; it++) {
        int i = tid + it * 384;
        int p = i >> 4, j = i & 15;
        vq[it] = __ldg(&q[(size_t)(pixbase + p) * 16 + j]);
        vk[it] = __ldg(&k[(size_t)(pixbase + p) * 16 + j]);
    }
}

__device__ __forceinline__ void qk_sts(u32* sm, const uint4 vq[8],
                                       const uint4 vk[8], int tid)
{
#pragma unroll
    for (int it = 0; it < 8; it++) {
        int i = tid + it * 384;
        int p = i >> 4, j = i & 15;
        int us = (j >> 1) ^ (p & 7);
        int qoff = p * 32 + us * 4 + (j & 1) * 2;
        *(uint2*)(sm + QSH_U + qoff) = make_uint2(vq[it].x, vq[it].z);
        *(uint2*)(sm + QSL_U + qoff) = make_uint2(vq[it].y, vq[it].w);
        int koff = p * 36 + 2 * j;
        *(uint2*)(sm + KH_U + koff) = make_uint2(vk[it].x, vk[it].z);
        *(uint2*)(sm + KL_U + koff) = make_uint2(vk[it].y, vk[it].w);
    }
}

__device__ __forceinline__ void compute_store_S(u32* sm, u32 smem_base,
                                                int wid, int lane)
{
    const int g = lane >> 2, t = lane & 3;
    const int w0 = wid * 16;
    const int tile = lane >> 3, lr = lane & 7;
    const int arow = w0 + lr + ((tile & 1) << 3);

    float acc[24][4];
#pragma unroll
    for (int n8 = 0; n8 < 24; n8++)
#pragma unroll
        for (int q = 0; q < 4; q++) acc[n8][q] = 0.f;

    const u32* kh = sm + KH_U;
    const u32* kl = sm + KL_U;

#pragma unroll
    for (int ch = 0; ch < 4; ch++) {
        const int ut = 2 * ch + (tile >> 1);
        const int us = ut ^ (arow & 7);
        const u32 qaddr = smem_base + (u32)(arow * 128 + us * 16);
        u32 ah[4], al[4];
        ldsm4(ah, qaddr);
        ldsm4(al, qaddr + 24576);
        const int kbase = ch * 8 + t;
#pragma unroll
        for (int n8 = 0; n8 < 24; n8++) {
            const int p36 = (n8 * 8 + g) * 36;
            u32 b0h = kh[p36 + kbase], b1h = kh[p36 + kbase + 4];
            u32 b0l = kl[p36 + kbase], b1l = kl[p36 + kbase + 4];
            mma16816(acc[n8], ah[0], ah[1], ah[2], ah[3], b0h, b1h);
            mma16816(acc[n8], ah[0], ah[1], ah[2], ah[3], b0l, b1l);
            mma16816(acc[n8], al[0], al[1], al[2], al[3], b0h, b1h);
        }
    }

    float m0 = -1e30f, m1 = -1e30f;
#pragma unroll
    for (int n8 = 0; n8 < 24; n8++) {
        m0 = fmaxf(m0, fmaxf(acc[n8][0], acc[n8][1]));
        m1 = fmaxf(m1, fmaxf(acc[n8][2], acc[n8][3]));
    }
    m0 = fmaxf(m0, __shfl_xor_sync(0xffffffffu, m0, 1));
    m0 = fmaxf(m0, __shfl_xor_sync(0xffffffffu, m0, 2));
    m1 = fmaxf(m1, __shfl_xor_sync(0xffffffffu, m1, 1));
    m1 = fmaxf(m1, __shfl_xor_sync(0xffffffffu, m1, 2));
    float s0 = 0.f, s1 = 0.f;
#pragma unroll
    for (int n8 = 0; n8 < 24; n8++) {
        acc[n8][0] = __expf(acc[n8][0] - m0);
        acc[n8][1] = __expf(acc[n8][1] - m0);
        acc[n8][2] = __expf(acc[n8][2] - m1);
        acc[n8][3] = __expf(acc[n8][3] - m1);
        s0 += acc[n8][0] + acc[n8][1];
        s1 += acc[n8][2] + acc[n8][3];
    }
    s0 += __shfl_xor_sync(0xffffffffu, s0, 1);
    s0 += __shfl_xor_sync(0xffffffffu, s0, 2);
    s1 += __shfl_xor_sync(0xffffffffu, s1, 1);
    s1 += __shfl_xor_sync(0xffffffffu, s1, 2);
    const float inv0 = 1.0f / s0, inv1 = 1.0f / s1;

    __syncthreads();   // all warps done reading Qs/Ks before S overwrites them

    u32* shp = sm;
    u32* slp = sm + SL_B / 4;
    const int rg = w0 + g;
#pragma unroll
    for (int n8 = 0; n8 < 24; n8++) {
        const int us = (n8 & 24) | ((n8 & 7) ^ (rg & 7));
        const int off = us * 4 + t;
        u32 h, l;
        split_pack(acc[n8][0] * inv0, acc[n8][1] * inv0, h, l);
        shp[rg * 96 + off] = h;
        slp[rg * 96 + off] = l;
        split_pack(acc[n8][2] * inv1, acc[n8][3] * inv1, h, l);
        shp[(rg + 8) * 96 + off] = h;
        slp[(rg + 8) * 96 + off] = l;
    }
}

// ---- v-pair F loads (prepacked; pure copy) ----
__device__ __forceinline__ void fv_ldg(uint4 fa[4], uint4 fb[4],
                                       const uint4* __restrict__ vh,
                                       const uint4* __restrict__ vl,
                                       int vbase4, int tid)
{
#pragma unroll
    for (int it = 0; it < 4; it++) {
        int i4 = tid + it * 384;
        int c = i4 / 24, q4 = i4 - c * 24;
        fa[it] = __ldg(&vh[vbase4 + c * 4608 + q4]);
        fb[it] = __ldg(&vl[vbase4 + c * 4608 + q4]);
    }
}

__device__ __forceinline__ void fv_sts(u32* sm, const uint4 fa[4],
                                       const uint4 fb[4], int tid)
{
#pragma unroll
    for (int it = 0; it < 4; it++) {
        int i4 = tid + it * 384;
        int c = i4 / 24, q4 = i4 - c * 24;
        *(uint4*)(sm + FH_U + c * 100 + q4 * 4) = fa[it];
        *(uint4*)(sm + FL_U + c * 100 + q4 * 4) = fb[it];
    }
}

// ---- fp32 single-source F load (stage-2 fused applies read outR / outL) ----
__device__ __forceinline__ void f1_ldg(float4 f[8], const float* __restrict__ s,
                                       int rb, int tid)
{
#pragma unroll
    for (int it = 0; it < 8; it++) {
        int i = tid + it * 384;
        int c = i / 48, q = i - c * 48;
        f[it] = *(const float4*)(s + rb + c * CS + q * 4);
    }
}

__device__ __forceinline__ void f1_sts(u32* sm, const float4 f[8], int tid)
{
#pragma unroll
    for (int it = 0; it < 8; it++) {
        int i = tid + it * 384;
        int c = i / 48, q = i - c * 48;
        u32 h0, l0, h1, l1;
        split_pack(f[it].x, f[it].y, h0, l0);
        split_pack(f[it].z, f[it].w, h1, l1);
        *(uint2*)(sm + FH_U + c * 100 + 2 * q) = make_uint2(h0, h1);
        *(uint2*)(sm + FL_U + c * 100 + 2 * q) = make_uint2(l0, l1);
    }
}

template <bool TR>
__device__ __forceinline__ void apply_tc(u32* sm, u32 smem_base,
                                         int wid, int lane, float acc[8][4])
{
    const int g = lane >> 2, t = lane & 3;
    const int w0 = wid * 16;
    const int tile = lane >> 3, lr = lane & 7;
    const u32* fh = sm + FH_U;
    const u32* fl = sm + FL_U;

#pragma unroll
    for (int n8 = 0; n8 < 8; n8++)
#pragma unroll
        for (int q = 0; q < 4; q++) acc[n8][q] = 0.f;

#pragma unroll
    for (int k = 0; k < 12; k++) {
        u32 ah[4], al[4];
        if (!TR) {
            const int row = w0 + lr + ((tile & 1) << 3);
            const int ut = 2 * k + (tile >> 1);
            const int us = (ut & 24) | ((ut & 7) ^ (row & 7));
            const u32 addr = smem_base + (u32)(row * 384 + us * 16);
            ldsm4(ah, addr);
            ldsm4(al, addr + 73728);
        } else {
            const int srow = k * 16 + lr + ((tile >> 1) << 3);
            const int cu = 2 * wid + (tile & 1);
            const int us = (cu & 24) | ((cu & 7) ^ (srow & 7));
            const u32 addr = smem_base + (u32)(srow * 384 + us * 16);
            ldsm4t(ah, addr);
            ldsm4t(al, addr + 73728);
        }
        const int fb = 8 * k + t;
#pragma unroll
        for (int n8 = 0; n8 < 8; n8++) {
            const int c100 = (n8 * 8 + g) * 100;
            u32 b0h = fh[c100 + fb], b1h = fh[c100 + fb + 4];
            u32 b0l = fl[c100 + fb], b1l = fl[c100 + fb + 4];
            mma16816(acc[n8], ah[0], ah[1], ah[2], ah[3], b0h, b1h);
            mma16816(acc[n8], ah[0], ah[1], ah[2], ah[3], b0l, b1l);
            mma16816(acc[n8], al[0], al[1], al[2], al[3], b0h, b1h);
        }
    }
}

__device__ __forceinline__ void emit_init2(float* dst, const float* base,
                                           const float acc[8][4],
                                           int rb, int wid, int lane)
{
    const int g = lane >> 2, t = lane & 3, w0 = wid * 16;
#pragma unroll
    for (int n8 = 0; n8 < 8; n8++)
#pragma unroll
        for (int q = 0; q < 4; q++) {
            const int c = n8 * 8 + 2 * t + (q & 1);
            const int w = w0 + g + ((q >> 1) << 3);
            const int off = rb + c * CS + w;
            dst[off] = base[off] + acc[n8][q];
        }
}

__device__ __forceinline__ void emit_add2(float* dst, const float acc[8][4],
                                          int rb, int wid, int lane)
{
    const int g = lane >> 2, t = lane & 3, w0 = wid * 16;
#pragma unroll
    for (int n8 = 0; n8 < 8; n8++)
#pragma unroll
        for (int q = 0; q < 4; q++) {
            const int c = n8 * 8 + 2 * t + (q & 1);
            const int w = w0 + g + ((q >> 1) << 3);
            dst[rb + c * CS + w] += acc[n8][q];
        }
}

__global__ void __launch_bounds__(384, 1) attn_tc(
    const float* __restrict__ low1, const float* __restrict__ low2,
    const uint4* __restrict__ qkp, const u32* __restrict__ lv,
    float* __restrict__ outL, float* __restrict__ outR)
{
    extern __shared__ u32 sm[];
    const int h = blockIdx.x, b = blockIdx.y;
    const int tid = threadIdx.x, wid = tid >> 5, lane = tid & 31;
    const int rb = b * 64 * CS + h * WW;
    const int pixbase = (b * HH + h) * WW;
    const int vbase4 = b * 64 * 4608 + h * 24;
    const u32 smem_base = (u32)__cvta_generic_to_shared(sm);
    const uint4* l1vh = (const uint4*)(lv + (size_t)0 * VPLANE);
    const uint4* l1vl = (const uint4*)(lv + (size_t)1 * VPLANE);
    const uint4* l2vh = (const uint4*)(lv + (size_t)2 * VPLANE);
    const uint4* l2vl = (const uint4*)(lv + (size_t)3 * VPLANE);
    float acc[8][4];

    // ---- stage 1: S1 = softmax(Q1^T K1) ----
    {
        uint4 vq[8], vk[8];
        qk_ldg(vq, vk, qkp + 0, qkp + (size_t)1 * NPIX * 16, pixbase, tid);
        qk_sts(sm, vq, vk, tid);
    }
    __syncthreads();
    compute_store_S(sm, smem_base, wid, lane);
    __syncthreads();

    // F = low2 (prepacked copy)
    {
        uint4 fa[4], fb[4];
        fv_ldg(fa, fb, l2vh, l2vl, vbase4, tid);
        fv_sts(sm, fa, fb, tid);
    }
    __syncthreads();
    apply_tc<false>(sm, smem_base, wid, lane, acc);
    __syncthreads();
    // overlap: load F=low1 while emitting outL (= low1 + r2l1 after this emit)
    {
        uint4 fa[4], fb[4];
        fv_ldg(fa, fb, l1vh, l1vl, vbase4, tid);
        emit_init2(outL, low1, acc, rb, wid, lane);
        fv_sts(sm, fa, fb, tid);
    }
    __syncthreads();
    apply_tc<true>(sm, smem_base, wid, lane, acc);
    __syncthreads();
    // overlap: stage Q2/K2 while emitting outR (= low2 + l2r1 after this emit)
    {
        uint4 vq[8], vk[8];
        qk_ldg(vq, vk, qkp + (size_t)2 * NPIX * 16, qkp + (size_t)3 * NPIX * 16,
               pixbase, tid);
        emit_init2(outR, low2, acc, rb, wid, lane);
        qk_sts(sm, vq, vk, tid);
    }
    __syncthreads();

    // ---- stage 2: S2 = softmax(Q2^T K2) ----
    compute_store_S(sm, smem_base, wid, lane);
    __syncthreads();

    // F = low2 + l2r1 == current outR (single-array read)
    {
        float4 f[8];
        f1_ldg(f, outR, rb, tid);
        f1_sts(sm, f, tid);
    }
    __syncthreads();
    apply_tc<false>(sm, smem_base, wid, lane, acc);
    __syncthreads();
    // F = low1 + r2l1 == current outL; must be fully read BEFORE emit_add2(outL)
    {
        float4 f[8];
        f1_ldg(f, outL, rb, tid);
        __syncthreads();                 // all outL reads complete before writes
        emit_add2(outL, acc, rb, wid, lane);
        f1_sts(sm, f, tid);
    }
    __syncthreads();
    apply_tc<true>(sm, smem_base, wid, lane, acc);
    emit_add2(outR, acc, rb, wid, lane);
}

// =================================================================================
extern "C" void kernel_launch(void* const* d_in, const int* in_sizes, int n_in,
                              void* d_out, int out_size)
{
    const float* low1   = (const float*)d_in[0];
    const float* low2   = (const float*)d_in[1];
    const float* fe1_w1 = (const float*)d_in[2];
    const float* fe1_b1 = (const float*)d_in[3];
    const float* fe1_w2 = (const float*)d_in[4];
    const float* fe1_b2 = (const float*)d_in[5];
    const float* fe2_w1 = (const float*)d_in[6];
    const float* fe2_b1 = (const float*)d_in[7];
    const float* fe2_w2 = (const float*)d_in[8];
    const float* fe2_b2 = (const float*)d_in[9];
    const float* conv_w = (const float*)d_in[10];
    const float* conv_b = (const float*)d_in[11];
    float* out = (float*)d_out;

    uint4 *low1p, *low2p, *tp, *ap, *qkp, *wp;
    u32 *lv;
    cudaGetSymbolAddress((void**)&low1p, g_low1p);
    cudaGetSymbolAddress((void**)&low2p, g_low2p);
    cudaGetSymbolAddress((void**)&tp,    g_tp);
    cudaGetSymbolAddress((void**)&ap,    g_ap);
    cudaGetSymbolAddress((void**)&qkp,   g_qkp);
    cudaGetSymbolAddress((void**)&wp,    g_wp);
    cudaGetSymbolAddress((void**)&lv,    g_lv);

    uint4* wp_fe1w1 = wp + 0 * 9216;
    uint4* wp_fe2w1 = wp + 1 * 9216;
    uint4* wp_fe1w2 = wp + 2 * 9216;
    uint4* wp_fe2w2 = wp + 3 * 9216;
    uint4* wp_convw = wp + 4 * 9216;

    cudaFuncSetAttribute(conv3x3_tc,
                         cudaFuncAttributeMaxDynamicSharedMemorySize,
                         CONV_SMEM_BYTES);
    cudaFuncSetAttribute(attn_tc,
                         cudaFuncAttributeMaxDynamicSharedMemorySize, ATTN_SMEM);

    const dim3 cgrid(WW / 16, HH / 16, 4 * BB);

    // single prep launch: weights + NHWC features + v-pair features
    prep_all<<<(PREP_TOTAL + 255) / 256, 256>>>(
        low1, low2, fe1_w1, fe2_w1, fe1_w2, fe2_w2, conv_w,
        low1p, low2p, lv, wp);

    conv3x3_tc<<<cgrid, 256, CONV_SMEM_BYTES>>>(
        low1p, low2p, 0, wp_fe1w1, wp_fe2w1, fe1_b1, fe2_b1,
        nullptr, nullptr, tp, 1);
    conv3x3_tc<<<cgrid, 256, CONV_SMEM_BYTES>>>(
        tp, tp, NPIX * 16, wp_fe1w2, wp_fe2w2, fe1_b2, fe2_b2,
        low1, low2, ap, 2);
    conv3x3_tc<<<cgrid, 256, CONV_SMEM_BYTES>>>(
        ap, ap, NPIX * 16, wp_convw, wp_convw, conv_b, conv_b,
        nullptr, nullptr, qkp, 3);

    attn_tc<<<dim3(HH, BB), 384, ATTN_SMEM>>>(
        low1, low2, qkp, lv, out, out + NT);
}